// round 3
// baseline (speedup 1.0000x reference)
#include <cuda_runtime.h>
#include <cuda_bf16.h>

// Problem constants
#define BATCH 8
#define HH 256
#define WW 256
#define NCH 7          // channels in x
#define NBR 6          // neighbor branches
#define HID 64         // hidden channels of conv1

#define TILE_W 32
#define TILE_H 8
#define SW 34          // TILE_W + 2 halo
#define SH 10          // TILE_H + 2 halo

// Scratch for the 7-channel "combined" tensor (allocation-free device global)
__device__ float g_comb[BATCH * NCH * HH * WW];

// ---------------- packed fp32x2 helpers (sm_103a FFMA2 path) ----------------
__device__ __forceinline__ unsigned long long pk1(float v) {
    unsigned long long r;
    unsigned u = __float_as_uint(v);
    asm("mov.b64 %0, {%1, %2};" : "=l"(r) : "r"(u), "r"(u));
    return r;
}
__device__ __forceinline__ unsigned long long pk2(float a, float b) {
    unsigned long long r;
    unsigned ua = __float_as_uint(a), ub = __float_as_uint(b);
    asm("mov.b64 %0, {%1, %2};" : "=l"(r) : "r"(ua), "r"(ub));
    return r;
}
__device__ __forceinline__ void unpk(unsigned long long p, float& a, float& b) {
    unsigned lo, hi;
    asm("mov.b64 {%0, %1}, %2;" : "=r"(lo), "=r"(hi) : "l"(p));
    a = __uint_as_float(lo);
    b = __uint_as_float(hi);
}
__device__ __forceinline__ unsigned long long fma2(unsigned long long a,
                                                   unsigned long long b,
                                                   unsigned long long c) {
    unsigned long long d;
    asm("fma.rn.f32x2 %0, %1, %2, %3;" : "=l"(d) : "l"(a), "l"(b), "l"(c));
    return d;
}

// ---------------------------------------------------------------------------
// Kernel 1: fused per-neighbor conv1(2->64,3x3) + ReLU + conv2(64->1,1x1)
//           + sigmoid + gate*check, writes "combined" (7 channels).
// One thread = one pixel. f32x2 packs output-channel pairs.
// ---------------------------------------------------------------------------
__global__ __launch_bounds__(256) void k_gate(
    const float* __restrict__ x,    // (B, 7, H, W)
    const float* __restrict__ W1,   // (6, 64, 2, 3, 3)
    const float* __restrict__ b1,   // (6, 64)
    const float* __restrict__ W2,   // (6, 1, 64, 1, 1)
    const float* __restrict__ b2)   // (6, 1)
{
    __shared__ __align__(16) float s_tile[NCH][SH][SW];          // 9520 B
    __shared__ __align__(16) float s_W1[NBR * 18 * HID];         // 27648 B, [j][t][o]
    __shared__ __align__(16) float s_b1[NBR * HID];              // 1536 B
    __shared__ __align__(16) float s_W2[NBR * HID];              // 1536 B
    __shared__ float s_b2[8];

    const int tid = threadIdx.y * TILE_W + threadIdx.x;

    // Load + transpose W1: src [(j*64+o)*18 + t] -> smem [(j*18+t)*64 + o]
    // t in [0,18) = ci*9 + tap
    for (int i = tid; i < NBR * HID * 18; i += 256) {
        int t  = i % 18;
        int jo = i / 18;
        int o  = jo % HID;
        int j  = jo / HID;
        s_W1[(j * 18 + t) * HID + o] = W1[i];
    }
    for (int i = tid; i < NBR * HID; i += 256) {
        s_b1[i] = b1[i];
        s_W2[i] = W2[i];
    }
    if (tid < NBR) s_b2[tid] = b2[tid];

    const int x0 = blockIdx.x * TILE_W;
    const int y0 = blockIdx.y * TILE_H;
    const int bz = blockIdx.z;
    const float* xb = x + (size_t)bz * NCH * HH * WW;

    // Cooperative halo tile load (SAME padding -> zeros)
    for (int i = tid; i < NCH * SH * SW; i += 256) {
        int sxx = i % SW;
        int r   = i / SW;
        int syy = r % SH;
        int c   = r / SH;
        int gx = x0 + sxx - 1;
        int gy = y0 + syy - 1;
        float v = 0.0f;
        if (gx >= 0 && gx < WW && gy >= 0 && gy < HH)
            v = xb[(c * HH + gy) * WW + gx];
        s_tile[c][syy][sxx] = v;
    }
    __syncthreads();

    const int tx = threadIdx.x, ty = threadIdx.y;
    const int gx = x0 + tx, gy = y0 + ty;

    // Base (center channel 3) taps, reused across all 6 branches
    float bt[9];
#pragma unroll
    for (int dy = 0; dy < 3; dy++)
#pragma unroll
        for (int dx = 0; dx < 3; dx++)
            bt[dy * 3 + dx] = s_tile[3][ty + dy][tx + dx];

    float* cb = g_comb + ((size_t)bz * NCH * HH + gy) * WW + gx;
    cb[3 * HH * WW] = bt[4];   // center channel passthrough

#pragma unroll 1
    for (int j = 0; j < NBR; j++) {
        const int cch = (j < 3) ? j : j + 1;   // check channel index in x
        float ct[9];
#pragma unroll
        for (int dy = 0; dy < 3; dy++)
#pragma unroll
            for (int dx = 0; dx < 3; dx++)
                ct[dy * 3 + dx] = s_tile[cch][ty + dy][tx + dx];

        // weight tap blocks: input-channel 0 taps at t=0..8, channel 1 at 9..17
        // j<3: channel0 = base, channel1 = check.  j>=3: swapped.
        const int tb = (j < 3) ? 0 : 9;
        const int tc = 9 - tb;

        // 32 packed accumulators = 64 hidden channels, init with bias pairs
        unsigned long long acc[HID / 2];
        const float* b1j = s_b1 + j * HID;
#pragma unroll
        for (int p = 0; p < HID / 2; p++) {
            float2 bb = *(const float2*)(b1j + 2 * p);
            acc[p] = pk2(bb.x, bb.y);
        }

        const float* __restrict__ wjb = s_W1 + (j * 18 + tb) * HID;
        const float* __restrict__ wjc = s_W1 + (j * 18 + tc) * HID;
#pragma unroll
        for (int k = 0; k < 9; k++) {
            const unsigned long long a0 = pk1(bt[k]);
            const unsigned long long a1 = pk1(ct[k]);
            const ulonglong2* __restrict__ wb = (const ulonglong2*)(wjb + k * HID);
            const ulonglong2* __restrict__ wc = (const ulonglong2*)(wjc + k * HID);
#pragma unroll
            for (int q = 0; q < 16; q++) {
                const ulonglong2 u = wb[q];
                const ulonglong2 v = wc[q];
                acc[2 * q]     = fma2(a0, u.x, acc[2 * q]);
                acc[2 * q]     = fma2(a1, v.x, acc[2 * q]);
                acc[2 * q + 1] = fma2(a0, u.y, acc[2 * q + 1]);
                acc[2 * q + 1] = fma2(a1, v.y, acc[2 * q + 1]);
            }
        }

        // ReLU + 1x1 conv (dot with W2) + sigmoid. 4 partial chains for ILP.
        const float* __restrict__ w2j = s_W2 + j * HID;
        float s0 = s_b2[j], s1 = 0.0f, s2 = 0.0f, s3 = 0.0f;
#pragma unroll
        for (int p = 0; p < HID / 2; p += 2) {
            float h0, h1, h2, h3;
            unpk(acc[p], h0, h1);
            unpk(acc[p + 1], h2, h3);
            const float4 w = *(const float4*)(w2j + 2 * p);
            s0 = fmaf(fmaxf(h0, 0.0f), w.x, s0);
            s1 = fmaf(fmaxf(h1, 0.0f), w.y, s1);
            s2 = fmaf(fmaxf(h2, 0.0f), w.z, s2);
            s3 = fmaf(fmaxf(h3, 0.0f), w.w, s3);
        }
        const float s = (s0 + s1) + (s2 + s3);
        const float sim = 1.0f / (1.0f + __expf(-s));

        const int oc = (j < 3) ? j : j + 1;   // combined channel
        cb[oc * HH * WW] = sim * ct[4];
    }
}

// ---------------------------------------------------------------------------
// Kernel 2: final 7->7 3x3 SAME conv over "combined".
// One thread = one pixel, all 7 output channels.
// ---------------------------------------------------------------------------
__global__ __launch_bounds__(256) void k_final(
    const float* __restrict__ Wm,   // (7, 7, 3, 3)
    const float* __restrict__ bm,   // (7,)
    float* __restrict__ out)        // (B, 7, H, W)
{
    __shared__ float s_tile[NCH][SH][SW];
    __shared__ float s_wm[NCH * NCH * 9];
    __shared__ float s_bm[8];

    const int tid = threadIdx.y * TILE_W + threadIdx.x;

    for (int i = tid; i < NCH * NCH * 9; i += 256) s_wm[i] = Wm[i];
    if (tid < NCH) s_bm[tid] = bm[tid];

    const int x0 = blockIdx.x * TILE_W;
    const int y0 = blockIdx.y * TILE_H;
    const int bz = blockIdx.z;
    const float* cb = g_comb + (size_t)bz * NCH * HH * WW;

    for (int i = tid; i < NCH * SH * SW; i += 256) {
        int sxx = i % SW;
        int r   = i / SW;
        int syy = r % SH;
        int c   = r / SH;
        int gx = x0 + sxx - 1;
        int gy = y0 + syy - 1;
        float v = 0.0f;
        if (gx >= 0 && gx < WW && gy >= 0 && gy < HH)
            v = cb[(c * HH + gy) * WW + gx];
        s_tile[c][syy][sxx] = v;
    }
    __syncthreads();

    const int tx = threadIdx.x, ty = threadIdx.y;
    const int gx = x0 + tx, gy = y0 + ty;

    float acc[NCH];
#pragma unroll
    for (int oc = 0; oc < NCH; oc++) acc[oc] = s_bm[oc];

#pragma unroll
    for (int ic = 0; ic < NCH; ic++) {
#pragma unroll
        for (int dy = 0; dy < 3; dy++) {
#pragma unroll
            for (int dx = 0; dx < 3; dx++) {
                const float v = s_tile[ic][ty + dy][tx + dx];
                const int t = dy * 3 + dx;
#pragma unroll
                for (int oc = 0; oc < NCH; oc++)
                    acc[oc] = fmaf(v, s_wm[(oc * NCH + ic) * 9 + t], acc[oc]);
            }
        }
    }

    float* ob = out + (size_t)bz * NCH * HH * WW;
#pragma unroll
    for (int oc = 0; oc < NCH; oc++)
        ob[(oc * HH + gy) * WW + gx] = acc[oc];
}

// ---------------------------------------------------------------------------
extern "C" void kernel_launch(void* const* d_in, const int* in_sizes, int n_in,
                              void* d_out, int out_size) {
    const float* x  = (const float*)d_in[0];
    const float* W1 = (const float*)d_in[1];
    const float* b1 = (const float*)d_in[2];
    const float* W2 = (const float*)d_in[3];
    const float* b2 = (const float*)d_in[4];
    const float* Wm = (const float*)d_in[5];
    const float* bm = (const float*)d_in[6];
    float* out = (float*)d_out;

    dim3 block(TILE_W, TILE_H);
    dim3 grid(WW / TILE_W, HH / TILE_H, BATCH);

    k_gate<<<grid, block>>>(x, W1, b1, W2, b2);
    k_final<<<grid, block>>>(Wm, bm, out);
}

// round 8
// speedup vs baseline: 2.1367x; 2.1367x over previous
#include <cuda_runtime.h>
#include <cuda_bf16.h>

#define BATCH 8
#define HH 256
#define WW 256
#define NCH 7
#define NBR 6
#define HID 64

// ------------------------- k_gate tiling -------------------------
#define TILE_W 32
#define TILE_H 8          // one warp per tile row
#define SW 34
#define SH 10

// scratch for "combined" (allocation-free)
__device__ float g_comb[BATCH * NCH * HH * WW];

__device__ __forceinline__ unsigned pack_bf16(float lo, float hi) {
    __nv_bfloat162 p = __floats2bfloat162_rn(lo, hi);  // .x = lo (low 16 bits)
    return *(unsigned*)&p;
}

__device__ __forceinline__ void mma_bf16(float* c, const unsigned* a, const unsigned* b) {
    asm volatile(
        "mma.sync.aligned.m16n8k16.row.col.f32.bf16.bf16.f32 "
        "{%0,%1,%2,%3}, {%4,%5,%6,%7}, {%8,%9}, {%0,%1,%2,%3};"
        : "+f"(c[0]), "+f"(c[1]), "+f"(c[2]), "+f"(c[3])
        : "r"(a[0]), "r"(a[1]), "r"(a[2]), "r"(a[3]), "r"(b[0]), "r"(b[1]));
}

// ---------------------------------------------------------------------------
// k_gate: conv1 (2->64, 3x3) via bf16 HMMA + ReLU + 1x1 dot + sigmoid + gate.
// CTA: 256 threads = 8 warps, tile 32x8 pixels, warp w owns tile row w.
// Per branch j: GEMM  h[p, o] = sum_t A[p,t] * W1[j][o][t],  t in [0,18) pad 32.
// ---------------------------------------------------------------------------
__global__ __launch_bounds__(256) void k_gate(
    const float* __restrict__ x,    // (B,7,H,W)
    const float* __restrict__ W1,   // (6,64,2,3,3) -> [j][o][18]
    const float* __restrict__ b1,   // (6,64)
    const float* __restrict__ W2,   // (6,64)
    const float* __restrict__ b2)   // (6,)
{
    __shared__ __align__(16) float s_tile[NCH][SH][SW];      // 9.5 KB
    // B fragments, lane-indexed: [j][nt(8)][ks(2)][r(2)][lane(32)] -> 6144 u32
    __shared__ __align__(16) unsigned s_Bfrag[NBR * 8 * 2 * 2 * 32];  // 24.6 KB
    __shared__ __align__(8) float2 s_b1w2[NBR * HID];        // (b1, w2) 3 KB
    __shared__ float s_b2[8];

    const int lane = threadIdx.x;        // 0..31
    const int w    = threadIdx.y;        // warp id = tile row, 0..7
    const int tid  = w * 32 + lane;

    // ---- precompute B fragments from gmem W1 ----
    for (int i = tid; i < NBR * 8 * 2 * 2 * 32; i += 256) {
        int l    = i & 31;
        int rest = i >> 5;
        int r  = rest & 1;  rest >>= 1;
        int ks = rest & 1;  rest >>= 1;
        int nt = rest & 7;  rest >>= 3;
        int j  = rest;                       // 0..5
        int n  = nt * 8 + (l >> 2);
        int k  = ks * 16 + (l & 3) * 2 + r * 8;
        const float* wj = W1 + (j * HID + n) * 18;
        float w0 = (k     < 18) ? wj[k]     : 0.0f;
        float w1 = (k + 1 < 18) ? wj[k + 1] : 0.0f;
        s_Bfrag[i] = pack_bf16(w0, w1);
    }
    for (int i = tid; i < NBR * HID; i += 256)
        s_b1w2[i] = make_float2(b1[i], W2[i]);
    if (tid < NBR) s_b2[tid] = b2[tid];

    // ---- halo tile load ----
    const int x0 = blockIdx.x * TILE_W;
    const int y0 = blockIdx.y * TILE_H;
    const int bz = blockIdx.z;
    const float* xb = x + (size_t)bz * NCH * HH * WW;
    for (int i = tid; i < NCH * SH * SW; i += 256) {
        int sxx = i % SW;
        int rr  = i / SW;
        int syy = rr % SH;
        int c   = rr / SH;
        int gx = x0 + sxx - 1;
        int gy = y0 + syy - 1;
        float v = 0.0f;
        if (gx >= 0 && gx < WW && gy >= 0 && gy < HH)
            v = xb[(c * HH + gy) * WW + gx];
        s_tile[c][syy][sxx] = v;
    }
    __syncthreads();

    const int gr = lane >> 2;       // 0..7  (A/C row within group)
    const int q  = lane & 3;        // 0..3  (k-pair / col-pair index)
    const int gyr = y0 + w;         // this warp's global row

    float* cb = g_comb + (size_t)bz * NCH * HH * WW;

    // base channel passthrough: each lane writes one pixel of this row
    cb[(3 * HH + gyr) * WW + (x0 + lane)] = s_tile[3][w + 1][lane + 1];

#pragma unroll 1
    for (int j = 0; j < NBR; j++) {
        const int cch = (j < 3) ? j : j + 1;
        const int ch0 = (j < 3) ? 3 : cch;   // W1 input-channel 0 source
        const int ch1 = (j < 3) ? cch : 3;   // W1 input-channel 1 source

        // cache this branch's B fragments: 8 nt x 2 ks x 2 regs = 32 regs
        unsigned B[8][2][2];
        const unsigned* bf = s_Bfrag + j * (8 * 2 * 2 * 32);
#pragma unroll
        for (int nt = 0; nt < 8; nt++)
#pragma unroll
            for (int ks = 0; ks < 2; ks++) {
                B[nt][ks][0] = bf[((nt * 2 + ks) * 2 + 0) * 32 + lane];
                B[nt][ks][1] = bf[((nt * 2 + ks) * 2 + 1) * 32 + lane];
            }

        const float2* bw = s_b1w2 + j * HID;

#pragma unroll
        for (int g = 0; g < 2; g++) {       // two m16 pixel groups per warp
            const int plo = g * 16 + gr;    // pixel (col in tile row)
            const int phi = plo + 8;

            // ---- A fragments ----
            // tap t: t<9 -> ch0 tap t; t>=9 -> ch1 tap t-9
            //   value = s_tile[ch][w + tt/3][px + tt%3]
            unsigned A0[4], A1[4];          // ks0, ks1
            {
                const int t0 = 2 * q;       // 0,2,4,6
#pragma unroll
                for (int h = 0; h < 2; h++) {   // h=0: cols t0..t0+1, h=1: +8
                    int ta = t0 + 8 * h;
                    int tb_ = ta + 1;
                    int ca = (ta >= 9) ? ch1 : ch0;  int tta = (ta >= 9) ? ta - 9 : ta;
                    int cb_ = (tb_ >= 9) ? ch1 : ch0; int ttb = (tb_ >= 9) ? tb_ - 9 : tb_;
                    float alo0 = s_tile[ca][w + tta / 3][plo + tta % 3];
                    float alo1 = s_tile[cb_][w + ttb / 3][plo + ttb % 3];
                    float ahi0 = s_tile[ca][w + tta / 3][phi + tta % 3];
                    float ahi1 = s_tile[cb_][w + ttb / 3][phi + ttb % 3];
                    A0[0 + h * 2] = pack_bf16(alo0, alo1);   // a0 (h=0), a2 (h=1)
                    A0[1 + h * 2] = pack_bf16(ahi0, ahi1);   // a1, a3
                }
                // ks1: only taps 16,17 (= ch1 taps 7,8) are real, held by q==0
                if (q == 0) {
                    float alo0 = s_tile[ch1][w + 2][plo + 1];  // tt=7: dy2,dx1
                    float alo1 = s_tile[ch1][w + 2][plo + 2];  // tt=8: dy2,dx2
                    float ahi0 = s_tile[ch1][w + 2][phi + 1];
                    float ahi1 = s_tile[ch1][w + 2][phi + 2];
                    A1[0] = pack_bf16(alo0, alo1);
                    A1[1] = pack_bf16(ahi0, ahi1);
                } else {
                    A1[0] = 0; A1[1] = 0;
                }
                A1[2] = 0; A1[3] = 0;
            }

            // ---- accumulate: init with conv1 bias, then 16 HMMA ----
            float acc[8][4];
#pragma unroll
            for (int nt = 0; nt < 8; nt++) {
                const float2 ba = bw[nt * 8 + 2 * q];
                const float2 bb = bw[nt * 8 + 2 * q + 1];
                acc[nt][0] = ba.x; acc[nt][1] = bb.x;
                acc[nt][2] = ba.x; acc[nt][3] = bb.x;
            }
#pragma unroll
            for (int nt = 0; nt < 8; nt++) {
                mma_bf16(acc[nt], A0, B[nt][0]);
                mma_bf16(acc[nt], A1, B[nt][1]);
            }

            // ---- epilogue: ReLU, dot with W2, quad reduce, sigmoid, gate ----
            float slo = 0.0f, shi = 0.0f;
#pragma unroll
            for (int nt = 0; nt < 8; nt++) {
                const float2 ba = bw[nt * 8 + 2 * q];
                const float2 bb = bw[nt * 8 + 2 * q + 1];
                slo = fmaf(fmaxf(acc[nt][0], 0.0f), ba.y, slo);
                slo = fmaf(fmaxf(acc[nt][1], 0.0f), bb.y, slo);
                shi = fmaf(fmaxf(acc[nt][2], 0.0f), ba.y, shi);
                shi = fmaf(fmaxf(acc[nt][3], 0.0f), bb.y, shi);
            }
            slo += __shfl_xor_sync(0xffffffffu, slo, 1);
            slo += __shfl_xor_sync(0xffffffffu, slo, 2);
            shi += __shfl_xor_sync(0xffffffffu, shi, 1);
            shi += __shfl_xor_sync(0xffffffffu, shi, 2);

            if (q == 0) {
                const float blo = slo + s_b2[j];
                const float bhi = shi + s_b2[j];
                const float siglo = 1.0f / (1.0f + __expf(-blo));
                const float sighi = 1.0f / (1.0f + __expf(-bhi));
                const float ctlo = s_tile[cch][w + 1][plo + 1];
                const float cthi = s_tile[cch][w + 1][phi + 1];
                const int oc = cch;   // combined channel index
                float* orow = cb + ((size_t)oc * HH + gyr) * WW + x0;
                orow[plo] = siglo * ctlo;
                orow[phi] = sighi * cthi;
            }
        }
    }
}

// ---------------------------------------------------------------------------
// k_final: 7->7 3x3 SAME conv.  4 px per thread, tile 128x8.
// ---------------------------------------------------------------------------
#define FT_W 128
#define FSW 136   // padded row stride (floats), 16B-aligned rows

__global__ __launch_bounds__(256) void k_final(
    const float* __restrict__ Wm,   // (7,7,3,3)
    const float* __restrict__ bm,   // (7,)
    float* __restrict__ out)        // (B,7,H,W)
{
    __shared__ __align__(16) float s_tile[NCH][SH][FSW];   // 38 KB
    __shared__ float s_wm[NCH * NCH * 9];
    __shared__ float s_bm[8];

    const int tx = threadIdx.x;     // 0..31
    const int ty = threadIdx.y;     // 0..7
    const int tid = ty * 32 + tx;

    for (int i = tid; i < NCH * NCH * 9; i += 256) s_wm[i] = Wm[i];
    if (tid < NCH) s_bm[tid] = bm[tid];

    const int x0 = blockIdx.x * FT_W;
    const int y0 = blockIdx.y * TILE_H;
    const int bz = blockIdx.z;
    const float* cbs = g_comb + (size_t)bz * NCH * HH * WW;

    // halo load: cols idx 0..129 <-> gx x0-1 .. x0+128
    for (int i = tid; i < NCH * SH * (FT_W + 2); i += 256) {
        int col = i % (FT_W + 2);
        int rr  = i / (FT_W + 2);
        int syy = rr % SH;
        int c   = rr / SH;
        int gx = x0 + col - 1;
        int gy = y0 + syy - 1;
        float v = 0.0f;
        if (gx >= 0 && gx < WW && gy >= 0 && gy < HH)
            v = cbs[(c * HH + gy) * WW + gx];
        s_tile[c][syy][col] = v;
    }
    __syncthreads();

    const int pxb = tx * 4;            // 4 consecutive pixels
    const int gy  = y0 + ty;

    float acc[NCH][4];
#pragma unroll
    for (int oc = 0; oc < NCH; oc++)
#pragma unroll
        for (int p = 0; p < 4; p++) acc[oc][p] = s_bm[oc];

#pragma unroll 1
    for (int ic = 0; ic < NCH; ic++) {
        // taps: rows ty..ty+2, cols pxb..pxb+5 (tile col = gx - x0 + 1)
        float t[3][6];
#pragma unroll
        for (int dy = 0; dy < 3; dy++) {
            const float* row = &s_tile[ic][ty + dy][0];
            float4 v4 = *(const float4*)(row + pxb);     // 16B aligned
            t[dy][0] = v4.x; t[dy][1] = v4.y; t[dy][2] = v4.z; t[dy][3] = v4.w;
            t[dy][4] = row[pxb + 4];
            t[dy][5] = row[pxb + 5];
        }
#pragma unroll
        for (int oc = 0; oc < NCH; oc++) {
            const float* wm = s_wm + (oc * NCH + ic) * 9;
#pragma unroll
            for (int dy = 0; dy < 3; dy++)
#pragma unroll
                for (int dx = 0; dx < 3; dx++) {
                    const float wv = wm[dy * 3 + dx];
#pragma unroll
                    for (int p = 0; p < 4; p++)
                        acc[oc][p] = fmaf(t[dy][p + dx], wv, acc[oc][p]);
                }
        }
    }

    float* ob = out + (size_t)bz * NCH * HH * WW;
#pragma unroll
    for (int oc = 0; oc < NCH; oc++) {
        float4 r = make_float4(acc[oc][0], acc[oc][1], acc[oc][2], acc[oc][3]);
        *(float4*)(ob + ((size_t)oc * HH + gy) * WW + x0 + pxb) = r;
    }
}

// ---------------------------------------------------------------------------
extern "C" void kernel_launch(void* const* d_in, const int* in_sizes, int n_in,
                              void* d_out, int out_size) {
    const float* x  = (const float*)d_in[0];
    const float* W1 = (const float*)d_in[1];
    const float* b1 = (const float*)d_in[2];
    const float* W2 = (const float*)d_in[3];
    const float* b2 = (const float*)d_in[4];
    const float* Wm = (const float*)d_in[5];
    const float* bm = (const float*)d_in[6];
    float* out = (float*)d_out;

    dim3 blk(32, 8);
    dim3 g1(WW / TILE_W, HH / TILE_H, BATCH);
    k_gate<<<g1, blk>>>(x, W1, b1, W2, b2);

    dim3 g2(WW / FT_W, HH / TILE_H, BATCH);
    k_final<<<g2, blk>>>(Wm, bm, out);
}

// round 11
// speedup vs baseline: 2.1836x; 1.0220x over previous
#include <cuda_runtime.h>
#include <cuda_bf16.h>

#define BATCH 8
#define HH 256
#define WW 256
#define NCH 7
#define NBR 6
#define HID 64

#define TILE_W 32
#define TILE_H 8
#define SW 34
#define SH 10
#define PLANE (SH * SW)   // floats per channel plane

__device__ float g_comb[BATCH * NCH * HH * WW];

__device__ __forceinline__ unsigned pack_bf16(float lo, float hi) {
    __nv_bfloat162 p = __floats2bfloat162_rn(lo, hi);
    return *(unsigned*)&p;
}

__device__ __forceinline__ void mma_bf16(float* c, const unsigned* a, const unsigned* b) {
    asm volatile(
        "mma.sync.aligned.m16n8k16.row.col.f32.bf16.bf16.f32 "
        "{%0,%1,%2,%3}, {%4,%5,%6,%7}, {%8,%9}, {%0,%1,%2,%3};"
        : "+f"(c[0]), "+f"(c[1]), "+f"(c[2]), "+f"(c[3])
        : "r"(a[0]), "r"(a[1]), "r"(a[2]), "r"(a[3]), "r"(b[0]), "r"(b[1]));
}

// ---------------------------------------------------------------------------
// k_gate: conv1 (2->64, 3x3) via bf16 HMMA + ReLU + 1x1 dot + sigmoid + gate.
// ---------------------------------------------------------------------------
__global__ __launch_bounds__(256) void k_gate(
    const float* __restrict__ x,
    const float* __restrict__ W1,   // (6,64,2,3,3)
    const float* __restrict__ b1,   // (6,64)
    const float* __restrict__ W2,   // (6,64)
    const float* __restrict__ b2)   // (6,)
{
    __shared__ __align__(16) float s_tile[NCH][SH][SW];
    // B fragments: [j][nt(8)][ks(2)][lane(32)][r(2)]  (r adjacent -> LDS.64)
    __shared__ __align__(16) unsigned s_Bfrag[NBR * 8 * 2 * 32 * 2];
    __shared__ __align__(8) float2 s_b1w2[NBR * HID];
    __shared__ float s_b2[8];

    const int lane = threadIdx.x;
    const int w    = threadIdx.y;
    const int tid  = w * 32 + lane;

    // ---- precompute B fragments ----
    for (int i = tid; i < NBR * 8 * 2 * 32 * 2; i += 256) {
        int r    = i & 1;  int rest = i >> 1;
        int l    = rest & 31; rest >>= 5;
        int ks   = rest & 1;  rest >>= 1;
        int nt   = rest & 7;  rest >>= 3;
        int j    = rest;
        int n  = nt * 8 + (l >> 2);
        int k  = ks * 16 + (l & 3) * 2 + r * 8;
        const float* wj = W1 + (j * HID + n) * 18;
        float w0 = (k     < 18) ? wj[k]     : 0.0f;
        float w1 = (k + 1 < 18) ? wj[k + 1] : 0.0f;
        s_Bfrag[i] = pack_bf16(w0, w1);
    }
    for (int i = tid; i < NBR * HID; i += 256)
        s_b1w2[i] = make_float2(b1[i], W2[i]);
    if (tid < NBR) s_b2[tid] = b2[tid];

    // ---- halo tile load ----
    const int x0 = blockIdx.x * TILE_W;
    const int y0 = blockIdx.y * TILE_H;
    const int bz = blockIdx.z;
    const float* xb = x + (size_t)bz * NCH * HH * WW;
    for (int i = tid; i < NCH * SH * SW; i += 256) {
        int sxx = i % SW;
        int rr  = i / SW;
        int syy = rr % SH;
        int c   = rr / SH;
        int gx = x0 + sxx - 1;
        int gy = y0 + syy - 1;
        float v = 0.0f;
        if (gx >= 0 && gx < WW && gy >= 0 && gy < HH)
            v = xb[(c * HH + gy) * WW + gx];
        s_tile[c][syy][sxx] = v;
    }
    __syncthreads();

    const int gr = lane >> 2;
    const int q  = lane & 3;
    const int gyr = y0 + w;

    float* cb = g_comb + (size_t)bz * NCH * HH * WW;
    cb[(3 * HH + gyr) * WW + (x0 + lane)] = s_tile[3][w + 1][lane + 1];

    // ---- per-thread tap spatial offsets (floats within a channel plane) ----
    // tap t: row = w + t/3, col = gr + t%3  (lo pixel of g=0)
    const float* splane = &s_tile[0][0][0];
    const int tA = 2 * q;
    const int tB = 2 * q + 1;
    const int tC = (q == 0) ? 8 : (2 * q - 1);
    const int offA = (w + tA / 3) * SW + (gr + tA % 3);
    const int offB = (w + tB / 3) * SW + (gr + tB % 3);
    const int offC = (w + tC / 3) * SW + (gr + tC % 3);
    const int off7 = (w + 2) * SW + (gr + 1);   // tap 7: dy2,dx1
    const int off8 = (w + 2) * SW + (gr + 2);   // tap 8: dy2,dx2
    const int off4 = (w + 1) * SW + (gr + 1);   // tap 4: center
    const bool q0 = (q == 0);

#pragma unroll 1
    for (int j = 0; j < NBR; j++) {
        const int cch = (j < 3) ? j : j + 1;
        const int ch0 = (j < 3) ? 3 : cch;   // W1 input-channel 0 source
        const int ch1 = (j < 3) ? cch : 3;   // W1 input-channel 1 source
        const int c0 = ch0 * PLANE;
        const int c1 = ch1 * PLANE;

        const float* pA = splane + offA + c0;            // h0 tap ta (ch0)
        const float* pB = splane + offB + c0;            // h0 tap tb (ch0)
        const float* pC = splane + offC + (q0 ? c0 : c1);// h1 tap ta
        const float* pD = splane + offA + c1;            // h1 tap tb (ch1, same spatial as tA)
        const float* p7 = splane + off7 + c1;
        const float* p8 = splane + off8 + c1;
        const float* pc4 = splane + off4 + cch * PLANE;

        // B fragments for this branch (LDS.64 pairs)
        unsigned B[8][2][2];
        const uint2* bf2 = (const uint2*)(s_Bfrag + j * (8 * 2 * 32 * 2));
#pragma unroll
        for (int nt = 0; nt < 8; nt++)
#pragma unroll
            for (int ks = 0; ks < 2; ks++) {
                uint2 v = bf2[(nt * 2 + ks) * 32 + lane];
                B[nt][ks][0] = v.x;
                B[nt][ks][1] = v.y;
            }

        const float2* bw = s_b1w2 + j * HID;

#pragma unroll
        for (int g = 0; g < 2; g++) {
            const int G = g * 16;            // float-offset for this m16 group
            const int plo = G + gr;
            const int phi = plo + 8;

            unsigned A0[4], A1[4];
            A0[0] = pack_bf16(pA[G],     pB[G]);
            A0[1] = pack_bf16(pA[G + 8], pB[G + 8]);
            A0[2] = pack_bf16(pC[G],     pD[G]);
            A0[3] = pack_bf16(pC[G + 8], pD[G + 8]);
            {
                unsigned a1lo = pack_bf16(p7[G],     p8[G]);
                unsigned a1hi = pack_bf16(p7[G + 8], p8[G + 8]);
                A1[0] = q0 ? a1lo : 0u;
                A1[1] = q0 ? a1hi : 0u;
                A1[2] = 0u; A1[3] = 0u;
            }

            float acc[8][4];
#pragma unroll
            for (int nt = 0; nt < 8; nt++) {
                const float2 ba = bw[nt * 8 + 2 * q];
                const float2 bb = bw[nt * 8 + 2 * q + 1];
                acc[nt][0] = ba.x; acc[nt][1] = bb.x;
                acc[nt][2] = ba.x; acc[nt][3] = bb.x;
            }
#pragma unroll
            for (int nt = 0; nt < 8; nt++) {
                mma_bf16(acc[nt], A0, B[nt][0]);
                mma_bf16(acc[nt], A1, B[nt][1]);
            }

            float slo = 0.0f, shi = 0.0f;
#pragma unroll
            for (int nt = 0; nt < 8; nt++) {
                const float2 ba = bw[nt * 8 + 2 * q];
                const float2 bb = bw[nt * 8 + 2 * q + 1];
                slo = fmaf(fmaxf(acc[nt][0], 0.0f), ba.y, slo);
                slo = fmaf(fmaxf(acc[nt][1], 0.0f), bb.y, slo);
                shi = fmaf(fmaxf(acc[nt][2], 0.0f), ba.y, shi);
                shi = fmaf(fmaxf(acc[nt][3], 0.0f), bb.y, shi);
            }
            slo += __shfl_xor_sync(0xffffffffu, slo, 1);
            slo += __shfl_xor_sync(0xffffffffu, slo, 2);
            shi += __shfl_xor_sync(0xffffffffu, shi, 1);
            shi += __shfl_xor_sync(0xffffffffu, shi, 2);

            if (q0) {
                const float blo = slo + s_b2[j];
                const float bhi = shi + s_b2[j];
                const float siglo = 1.0f / (1.0f + __expf(-blo));
                const float sighi = 1.0f / (1.0f + __expf(-bhi));
                const float ctlo = pc4[G];
                const float cthi = pc4[G + 8];
                float* orow = cb + ((size_t)cch * HH + gyr) * WW + x0;
                orow[plo] = siglo * ctlo;
                orow[phi] = sighi * cthi;
            }
        }
    }
}

// ---------------------------------------------------------------------------
// k_final: 7->7 3x3 SAME conv.  4 px per thread, tile 128x8, ic fully unrolled.
// ---------------------------------------------------------------------------
#define FT_W 128
#define FSW 136

__global__ __launch_bounds__(256) void k_final(
    const float* __restrict__ Wm,
    const float* __restrict__ bm,
    float* __restrict__ out)
{
    __shared__ __align__(16) float s_tile[NCH][SH][FSW];
    __shared__ float s_wm[NCH * NCH * 9];
    __shared__ float s_bm[8];

    const int tx = threadIdx.x;
    const int ty = threadIdx.y;
    const int tid = ty * 32 + tx;

    for (int i = tid; i < NCH * NCH * 9; i += 256) s_wm[i] = Wm[i];
    if (tid < NCH) s_bm[tid] = bm[tid];

    const int x0 = blockIdx.x * FT_W;
    const int y0 = blockIdx.y * TILE_H;
    const int bz = blockIdx.z;
    const float* cbs = g_comb + (size_t)bz * NCH * HH * WW;

    for (int i = tid; i < NCH * SH * (FT_W + 2); i += 256) {
        int col = i % (FT_W + 2);
        int rr  = i / (FT_W + 2);
        int syy = rr % SH;
        int c   = rr / SH;
        int gx = x0 + col - 1;
        int gy = y0 + syy - 1;
        float v = 0.0f;
        if (gx >= 0 && gx < WW && gy >= 0 && gy < HH)
            v = cbs[(c * HH + gy) * WW + gx];
        s_tile[c][syy][col] = v;
    }
    __syncthreads();

    const int pxb = tx * 4;
    const int gy  = y0 + ty;

    float acc[NCH][4];
#pragma unroll
    for (int oc = 0; oc < NCH; oc++)
#pragma unroll
        for (int p = 0; p < 4; p++) acc[oc][p] = s_bm[oc];

#pragma unroll
    for (int ic = 0; ic < NCH; ic++) {
        float t[3][6];
#pragma unroll
        for (int dy = 0; dy < 3; dy++) {
            const float* row = &s_tile[ic][ty + dy][0];
            float4 v4 = *(const float4*)(row + pxb);
            float2 v2 = *(const float2*)(row + pxb + 4);
            t[dy][0] = v4.x; t[dy][1] = v4.y; t[dy][2] = v4.z; t[dy][3] = v4.w;
            t[dy][4] = v2.x; t[dy][5] = v2.y;
        }
#pragma unroll
        for (int oc = 0; oc < NCH; oc++) {
            const float* wm = s_wm + (oc * NCH + ic) * 9;
#pragma unroll
            for (int dy = 0; dy < 3; dy++)
#pragma unroll
                for (int dx = 0; dx < 3; dx++) {
                    const float wv = wm[dy * 3 + dx];
#pragma unroll
                    for (int p = 0; p < 4; p++)
                        acc[oc][p] = fmaf(t[dy][p + dx], wv, acc[oc][p]);
                }
        }
    }

    float* ob = out + (size_t)bz * NCH * HH * WW;
#pragma unroll
    for (int oc = 0; oc < NCH; oc++) {
        float4 r = make_float4(acc[oc][0], acc[oc][1], acc[oc][2], acc[oc][3]);
        *(float4*)(ob + ((size_t)oc * HH + gy) * WW + x0 + pxb) = r;
    }
}

// ---------------------------------------------------------------------------
extern "C" void kernel_launch(void* const* d_in, const int* in_sizes, int n_in,
                              void* d_out, int out_size) {
    const float* x  = (const float*)d_in[0];
    const float* W1 = (const float*)d_in[1];
    const float* b1 = (const float*)d_in[2];
    const float* W2 = (const float*)d_in[3];
    const float* b2 = (const float*)d_in[4];
    const float* Wm = (const float*)d_in[5];
    const float* bm = (const float*)d_in[6];
    float* out = (float*)d_out;

    dim3 blk(32, 8);
    dim3 g1(WW / TILE_W, HH / TILE_H, BATCH);
    k_gate<<<g1, blk>>>(x, W1, b1, W2, b2);

    dim3 g2(WW / FT_W, HH / TILE_H, BATCH);
    k_final<<<g2, blk>>>(Wm, bm, out);
}